// round 1
// baseline (speedup 1.0000x reference)
#include <cuda_runtime.h>
#include <cuda_bf16.h>

#define N_NODES 100000
#define D 128

// Scratch: neighbor-sum accumulator (51.2 MB), static device global (no runtime alloc).
__device__ float g_neigh[(size_t)N_NODES * D];

// ---------------------------------------------------------------------------
// Kernel 1: zero the accumulator
// ---------------------------------------------------------------------------
__global__ void zero_neigh_kernel() {
    size_t total4 = (size_t)N_NODES * D / 4;
    size_t i = (size_t)blockIdx.x * blockDim.x + threadIdx.x;
    float4 z = make_float4(0.f, 0.f, 0.f, 0.f);
    for (; i < total4; i += (size_t)gridDim.x * blockDim.x) {
        reinterpret_cast<float4*>(g_neigh)[i] = z;
    }
}

// ---------------------------------------------------------------------------
// Kernel 2: edge scatter. One warp handles one edge per iteration:
// each lane moves 4 floats (float4 gather + red.global.add.v4.f32 scatter).
// Gather is coalesced (32 lanes cover the 512B row); atomics are 16B vector
// reductions to random L2 lines.
// ---------------------------------------------------------------------------
__global__ void scatter_kernel(const float* __restrict__ feat,
                               const int* __restrict__ src,
                               const int* __restrict__ dst,
                               int n_edges) {
    long long total = (long long)n_edges * 32;
    long long stride = (long long)gridDim.x * blockDim.x;
    for (long long i = (long long)blockIdx.x * blockDim.x + threadIdx.x;
         i < total; i += stride) {
        int e    = (int)(i >> 5);
        int lane = (int)(i & 31);
        int s = src[e];   // warp-uniform (all lanes same e) -> L1 broadcast
        int d = dst[e];
        float4 v = *reinterpret_cast<const float4*>(feat + (size_t)s * D + lane * 4);
        float* p = g_neigh + (size_t)d * D + lane * 4;
        asm volatile("red.global.add.v4.f32 [%0], {%1,%2,%3,%4};"
                     :: "l"(p), "f"(v.x), "f"(v.y), "f"(v.z), "f"(v.w)
                     : "memory");
    }
}

// ---------------------------------------------------------------------------
// Kernel 3: fused MLP. Per block: 64-row tile.
//   h = (1+eps)*feat + neigh           (loaded into smem, stride 132 to dodge
//                                       bank conflicts)
//   t = relu(h @ W1 + b1)              (acc in regs, written back over h tile)
//   out = t @ W2 + b2
// W1, W2 staged in smem (64 KB each). 256 threads, 4x8 micro-tile per thread.
// ---------------------------------------------------------------------------
#define TILE_M   64
#define H_STRIDE 132
#define MLP_THREADS 256

// smem layout (floats): [0, 128*128) W1 | [16384, 32768) W2 | [32768, +64*132) h/t
#define SMEM_FLOATS (128*128 + 128*128 + TILE_M*H_STRIDE)

__global__ __launch_bounds__(MLP_THREADS, 1)
void mlp_kernel(const float* __restrict__ feat,
                const float* __restrict__ epsp,
                const float* __restrict__ W1,
                const float* __restrict__ b1,
                const float* __restrict__ W2,
                const float* __restrict__ b2,
                float* __restrict__ out) {
    extern __shared__ float smem[];
    float* sW1 = smem;
    float* sW2 = smem + 128 * 128;
    float* sh  = smem + 2 * 128 * 128;

    const int tid = threadIdx.x;
    const int tm  = tid >> 4;          // 0..15
    const int tn  = tid & 15;          // 0..15
    const int m0  = tm * 4;
    const int n0  = tn * 8;
    const int row_base = blockIdx.x * TILE_M;
    const float eps1 = 1.0f + epsp[0];

    // Stage W1 and W2 (linear, float4)
    {
        const float4* gW1 = reinterpret_cast<const float4*>(W1);
        const float4* gW2 = reinterpret_cast<const float4*>(W2);
        float4* s1 = reinterpret_cast<float4*>(sW1);
        float4* s2 = reinterpret_cast<float4*>(sW2);
        for (int i = tid; i < 128 * 128 / 4; i += MLP_THREADS) {
            s1[i] = gW1[i];
            s2[i] = gW2[i];
        }
    }

    // Stage h tile: h = (1+eps)*feat + neigh. Rows past N_NODES -> 0.
    for (int i = tid; i < TILE_M * 32; i += MLP_THREADS) {
        int r  = i >> 5;          // 0..63
        int c4 = i & 31;          // float4 column index
        int m  = row_base + r;
        float4 v;
        if (m < N_NODES) {
            float4 f = *reinterpret_cast<const float4*>(feat   + (size_t)m * D + c4 * 4);
            float4 n = *reinterpret_cast<const float4*>(g_neigh + (size_t)m * D + c4 * 4);
            v = make_float4(eps1 * f.x + n.x, eps1 * f.y + n.y,
                            eps1 * f.z + n.z, eps1 * f.w + n.w);
        } else {
            v = make_float4(0.f, 0.f, 0.f, 0.f);
        }
        *reinterpret_cast<float4*>(sh + r * H_STRIDE + c4 * 4) = v;
    }
    __syncthreads();

    // ---- GEMM 1: t = relu(h @ W1 + b1) ----
    float acc[4][8];
#pragma unroll
    for (int i = 0; i < 4; i++)
#pragma unroll
        for (int j = 0; j < 8; j++) acc[i][j] = 0.f;

#pragma unroll 4
    for (int k = 0; k < 128; k++) {
        float a0 = sh[(m0 + 0) * H_STRIDE + k];
        float a1 = sh[(m0 + 1) * H_STRIDE + k];
        float a2 = sh[(m0 + 2) * H_STRIDE + k];
        float a3 = sh[(m0 + 3) * H_STRIDE + k];
        float4 w0 = *reinterpret_cast<const float4*>(sW1 + k * 128 + n0);
        float4 w1 = *reinterpret_cast<const float4*>(sW1 + k * 128 + n0 + 4);
        float w[8] = {w0.x, w0.y, w0.z, w0.w, w1.x, w1.y, w1.z, w1.w};
#pragma unroll
        for (int j = 0; j < 8; j++) {
            acc[0][j] = fmaf(a0, w[j], acc[0][j]);
            acc[1][j] = fmaf(a1, w[j], acc[1][j]);
            acc[2][j] = fmaf(a2, w[j], acc[2][j]);
            acc[3][j] = fmaf(a3, w[j], acc[3][j]);
        }
    }
    __syncthreads();   // all reads of h done before we overwrite it with t

    {
        float bj[8];
#pragma unroll
        for (int j = 0; j < 8; j++) bj[j] = b1[n0 + j];
#pragma unroll
        for (int i = 0; i < 4; i++)
#pragma unroll
            for (int j = 0; j < 8; j++) {
                float t = acc[i][j] + bj[j];
                sh[(m0 + i) * H_STRIDE + n0 + j] = t > 0.f ? t : 0.f;
            }
    }
    __syncthreads();

    // ---- GEMM 2: out = t @ W2 + b2 ----
#pragma unroll
    for (int i = 0; i < 4; i++)
#pragma unroll
        for (int j = 0; j < 8; j++) acc[i][j] = 0.f;

#pragma unroll 4
    for (int k = 0; k < 128; k++) {
        float a0 = sh[(m0 + 0) * H_STRIDE + k];
        float a1 = sh[(m0 + 1) * H_STRIDE + k];
        float a2 = sh[(m0 + 2) * H_STRIDE + k];
        float a3 = sh[(m0 + 3) * H_STRIDE + k];
        float4 w0 = *reinterpret_cast<const float4*>(sW2 + k * 128 + n0);
        float4 w1 = *reinterpret_cast<const float4*>(sW2 + k * 128 + n0 + 4);
        float w[8] = {w0.x, w0.y, w0.z, w0.w, w1.x, w1.y, w1.z, w1.w};
#pragma unroll
        for (int j = 0; j < 8; j++) {
            acc[0][j] = fmaf(a0, w[j], acc[0][j]);
            acc[1][j] = fmaf(a1, w[j], acc[1][j]);
            acc[2][j] = fmaf(a2, w[j], acc[2][j]);
            acc[3][j] = fmaf(a3, w[j], acc[3][j]);
        }
    }

    {
        float bj[8];
#pragma unroll
        for (int j = 0; j < 8; j++) bj[j] = b2[n0 + j];
#pragma unroll
        for (int i = 0; i < 4; i++) {
            int m = row_base + m0 + i;
            if (m < N_NODES) {
                float4 o0 = make_float4(acc[i][0] + bj[0], acc[i][1] + bj[1],
                                        acc[i][2] + bj[2], acc[i][3] + bj[3]);
                float4 o1 = make_float4(acc[i][4] + bj[4], acc[i][5] + bj[5],
                                        acc[i][6] + bj[6], acc[i][7] + bj[7]);
                *reinterpret_cast<float4*>(out + (size_t)m * D + n0)     = o0;
                *reinterpret_cast<float4*>(out + (size_t)m * D + n0 + 4) = o1;
            }
        }
    }
}

// ---------------------------------------------------------------------------
extern "C" void kernel_launch(void* const* d_in, const int* in_sizes, int n_in,
                              void* d_out, int out_size) {
    const float* feat = (const float*)d_in[0];
    const int*   src  = (const int*)d_in[1];
    const int*   dst  = (const int*)d_in[2];
    const float* eps  = (const float*)d_in[3];
    const float* W1   = (const float*)d_in[4];
    const float* b1   = (const float*)d_in[5];
    const float* W2   = (const float*)d_in[6];
    const float* b2   = (const float*)d_in[7];
    float*       out  = (float*)d_out;

    int n_edges = in_sizes[1];

    // 1) zero accumulator
    {
        int total4 = N_NODES * D / 4;
        int blocks = (total4 + 255) / 256;
        if (blocks > 8192) blocks = 8192;
        zero_neigh_kernel<<<blocks, 256>>>();
    }

    // 2) scatter-add messages
    scatter_kernel<<<2368, 256>>>(feat, src, dst, n_edges);

    // 3) fused MLP
    {
        size_t smem_bytes = (size_t)SMEM_FLOATS * sizeof(float);
        cudaFuncSetAttribute(mlp_kernel,
                             cudaFuncAttributeMaxDynamicSharedMemorySize,
                             (int)smem_bytes);
        int blocks = (N_NODES + TILE_M - 1) / TILE_M;
        mlp_kernel<<<blocks, MLP_THREADS, smem_bytes>>>(feat, eps, W1, b1, W2, b2, out);
    }
}